// round 2
// baseline (speedup 1.0000x reference)
#include <cuda_runtime.h>
#include <cstdint>

// ---------------------------------------------------------------------------
// SetAbstraction (PointNet++): FPS -> ball query (radius, first-K) -> MLP -> max
// B=2, N=16384, S=4096, K=32, F_IN=16, hidden 64-64-128
// ---------------------------------------------------------------------------

#define BB   2
#define NN   16384
#define SS   4096
#define KK   32
#define FIN  16
#define HID  64
#define HOUT 128

// ---- scratch (no allocations allowed; __device__ globals) ------------------
__device__ float g_centers[BB * SS * 3];
__device__ int   g_nbr[BB * SS * KK];
__device__ int   g_cnt[BB * SS];

// ===========================================================================
// Kernel 1: Farthest Point Sampling — one block per batch, 1024 threads.
// Coords live in shared (192KB), per-thread dmin (16) in registers.
// Exactly matches jnp: d = dx*dx + dy*dy + dz*dz (no FMA contraction),
// dmin = min(dmin, d), argmax with first-index (lowest index) tie-break.
// ===========================================================================
__global__ void __launch_bounds__(1024, 1)
fps_kernel(const float* __restrict__ pos, float* __restrict__ out_centers)
{
    extern __shared__ float sm[];
    float* s_xy = sm;           // 2*NN floats, interleaved (x,y)
    float* s_z  = sm + 2 * NN;  // NN floats

    __shared__ float s_wv[32];
    __shared__ int   s_wi[32];
    __shared__ int   s_selS;

    const int b   = blockIdx.x;
    const int tid = threadIdx.x;
    const float* pb = pos + (size_t)b * NN * 3;

    float dmin[16];
#pragma unroll
    for (int k = 0; k < 16; k++) {
        int p = (k << 10) + tid;
        float x_ = pb[p * 3 + 0];
        float y_ = pb[p * 3 + 1];
        float z_ = pb[p * 3 + 2];
        s_xy[2 * p + 0] = x_;
        s_xy[2 * p + 1] = y_;
        s_z[p] = z_;
        dmin[k] = 1e10f;
    }
    __syncthreads();

    int sel = 0;
    if (tid == 0) {
        int row = b * SS;
        float ox = s_xy[0], oy = s_xy[1], oz = s_z[0];
        out_centers[row * 3 + 0] = ox; out_centers[row * 3 + 1] = oy; out_centers[row * 3 + 2] = oz;
        g_centers[row * 3 + 0] = ox;   g_centers[row * 3 + 1] = oy;   g_centers[row * 3 + 2] = oz;
    }

    for (int t = 1; t < SS; t++) {
        float cx = s_xy[2 * sel + 0];
        float cy = s_xy[2 * sel + 1];
        float cz = s_z[sel];
        float ncx = -cx, ncy = -cy, ncz = -cz;

        float bv = -1.0f;
        int   bk = 0;
#pragma unroll
        for (int k = 0; k < 16; k++) {
            int p = (k << 10) + tid;
            float2 xy = *reinterpret_cast<const float2*>(&s_xy[2 * p]);
            float z_  = s_z[p];
            float dx = __fadd_rn(xy.x, ncx);
            float dy = __fadd_rn(xy.y, ncy);
            float dz = __fadd_rn(z_,   ncz);
            float d  = __fadd_rn(__fadd_rn(__fmul_rn(dx, dx), __fmul_rn(dy, dy)),
                                 __fmul_rn(dz, dz));
            float dm = fminf(dmin[k], d);
            dmin[k] = dm;
            if (dm > bv) { bv = dm; bk = k; }  // strict > keeps smallest k (smallest idx)
        }
        int bi = (bk << 10) + tid;

        // warp reduce: max value, tie -> smaller index
#pragma unroll
        for (int off = 16; off > 0; off >>= 1) {
            float ov = __shfl_down_sync(0xffffffffu, bv, off);
            int   oi = __shfl_down_sync(0xffffffffu, bi, off);
            if (ov > bv || (ov == bv && oi < bi)) { bv = ov; bi = oi; }
        }
        if ((tid & 31) == 0) { s_wv[tid >> 5] = bv; s_wi[tid >> 5] = bi; }
        __syncthreads();
        if (tid < 32) {
            bv = s_wv[tid]; bi = s_wi[tid];
#pragma unroll
            for (int off = 16; off > 0; off >>= 1) {
                float ov = __shfl_down_sync(0xffffffffu, bv, off);
                int   oi = __shfl_down_sync(0xffffffffu, bi, off);
                if (ov > bv || (ov == bv && oi < bi)) { bv = ov; bi = oi; }
            }
            if (tid == 0) s_selS = bi;
        }
        __syncthreads();
        sel = s_selS;
        if (tid == 0) {
            int row = b * SS + t;
            float ox = s_xy[2 * sel + 0], oy = s_xy[2 * sel + 1], oz = s_z[sel];
            out_centers[row * 3 + 0] = ox; out_centers[row * 3 + 1] = oy; out_centers[row * 3 + 2] = oz;
            g_centers[row * 3 + 0] = ox;   g_centers[row * 3 + 1] = oy;   g_centers[row * 3 + 2] = oz;
        }
    }
}

// ===========================================================================
// Kernel 2: Ball query — one warp per center; ordered scan, first K within R.
// Self-loop exclusion: global src (b*N+j) == global dst (b*S+s)  =>
//   j == s - b*(N-S). Early exit once cnt == K.
// ===========================================================================
__global__ void __launch_bounds__(256, 8)
ballq_kernel(const float* __restrict__ pos, float* __restrict__ out_batch)
{
    const int w    = (blockIdx.x * blockDim.x + threadIdx.x) >> 5;  // global warp = center
    const int lane = threadIdx.x & 31;
    if (w >= BB * SS) return;

    const int b = w >> 12;       // / SS
    const int s = w & (SS - 1);
    const float* pb = pos + (size_t)b * NN * 3;

    const float cx = g_centers[w * 3 + 0];
    const float cy = g_centers[w * 3 + 1];
    const float cz = g_centers[w * 3 + 2];
    const float R2 = (float)(0.1 * 0.1);   // 0.009999999776... (matches jnp f32(R*R))
    const int excl = s - b * (NN - SS);    // b=0: s ; b=1: negative (never hits)

    int cnt = 0;
    for (int j0 = 0; j0 < NN && cnt < KK; j0 += 32) {
        int j = j0 + lane;
        float x_ = pb[j * 3 + 0];
        float y_ = pb[j * 3 + 1];
        float z_ = pb[j * 3 + 2];
        float dx = __fsub_rn(cx, x_);
        float dy = __fsub_rn(cy, y_);
        float dz = __fsub_rn(cz, z_);
        float d2 = __fadd_rn(__fadd_rn(__fmul_rn(dx, dx), __fmul_rn(dy, dy)),
                             __fmul_rn(dz, dz));
        bool hit = (d2 <= R2) && (j != excl);
        unsigned m = __ballot_sync(0xffffffffu, hit);
        while (m && cnt < KK) {
            int bit = __ffs(m) - 1;
            if (lane == bit) g_nbr[w * KK + cnt] = j0 + bit;
            cnt++;
            m &= m - 1;
        }
    }
    if (lane == 0) {
        g_cnt[w] = cnt;
        out_batch[w] = (float)b;
    }
}

// ===========================================================================
// Kernel 3: gather + MLP(19->64->64->128, relu,relu,linear) + max over K+1.
// One warp per center; 4 edges register-blocked per pass (weights in SMEM
// amortized 4x). Self edge uses flat row b*S+s (PyG add_self_loops quirk).
// ===========================================================================
__global__ void __launch_bounds__(256, 1)
mlp_kernel(const float* __restrict__ x, const float* __restrict__ pos,
           const float* __restrict__ W1, const float* __restrict__ B1,
           const float* __restrict__ W2, const float* __restrict__ B2,
           const float* __restrict__ W3, const float* __restrict__ B3,
           float* __restrict__ out_x)
{
    extern __shared__ float sw[];
    float* sW1 = sw;               // 19*64 = 1216
    float* sb1 = sW1 + 19 * 64;    // 64
    float* sW2 = sb1 + 64;         // 4096
    float* sb2 = sW2 + 4096;       // 64
    float* sW3 = sb2 + 64;         // 8192
    float* sb3 = sW3 + 8192;       // 128

    const int tid = threadIdx.x;
    for (int i = tid; i < 19 * 64; i += 256) sW1[i] = W1[i];
    for (int i = tid; i < 64;      i += 256) sb1[i] = B1[i];
    for (int i = tid; i < 64 * 64; i += 256) sW2[i] = W2[i];
    for (int i = tid; i < 64;      i += 256) sb2[i] = B2[i];
    for (int i = tid; i < 64 * 128; i += 256) sW3[i] = W3[i];
    for (int i = tid; i < 128;     i += 256) sb3[i] = B3[i];
    __syncthreads();

    const int lane = tid & 31;
    const int c    = blockIdx.x * 8 + (tid >> 5);   // center id (grid sized so c < BB*SS)
    const int b    = c >> 12;
    const int s    = c & (SS - 1);

    const float cx = g_centers[c * 3 + 0];
    const float cy = g_centers[c * 3 + 1];
    const float cz = g_centers[c * 3 + 2];
    const float ccomp = (lane == 16) ? cx : ((lane == 17) ? cy : cz);
    const int cnt = g_cnt[c];

    float m0 = -3.0e38f, m1 = -3.0e38f, m2 = -3.0e38f, m3 = -3.0e38f;

    auto process4 = [&](const int rows[4], int nv) {
        // gather features: lanes 0..15 -> x_j, lanes 16..18 -> (p_j - center)
        float fv[4];
#pragma unroll
        for (int e = 0; e < 4; e++) {
            int r = rows[e];
            float v = 0.f;
            if (lane < FIN)          v = x[(size_t)r * FIN + lane];
            else if (lane < FIN + 3) v = pos[(size_t)r * 3 + (lane - FIN)] - ccomp;
            fv[e] = (e < nv) ? v : 0.f;
        }
        // layer 1: 19 -> 64, relu  (lane owns outputs lane, lane+32)
        float a0[4], a1[4];
#pragma unroll
        for (int e = 0; e < 4; e++) { a0[e] = sb1[lane]; a1[e] = sb1[lane + 32]; }
#pragma unroll
        for (int i = 0; i < FIN + 3; i++) {
            float w0 = sW1[i * 64 + lane];
            float w1 = sW1[i * 64 + 32 + lane];
#pragma unroll
            for (int e = 0; e < 4; e++) {
                float v = __shfl_sync(0xffffffffu, fv[e], i);
                a0[e] = fmaf(v, w0, a0[e]);
                a1[e] = fmaf(v, w1, a1[e]);
            }
        }
#pragma unroll
        for (int e = 0; e < 4; e++) { a0[e] = fmaxf(a0[e], 0.f); a1[e] = fmaxf(a1[e], 0.f); }

        // layer 2: 64 -> 64, relu
        float g0[4], g1[4];
#pragma unroll
        for (int e = 0; e < 4; e++) { g0[e] = sb2[lane]; g1[e] = sb2[lane + 32]; }
#pragma unroll
        for (int i = 0; i < 64; i++) {
            float w0 = sW2[i * 64 + lane];
            float w1 = sW2[i * 64 + 32 + lane];
#pragma unroll
            for (int e = 0; e < 4; e++) {
                float v = (i < 32) ? __shfl_sync(0xffffffffu, a0[e], i)
                                   : __shfl_sync(0xffffffffu, a1[e], i - 32);
                g0[e] = fmaf(v, w0, g0[e]);
                g1[e] = fmaf(v, w1, g1[e]);
            }
        }
#pragma unroll
        for (int e = 0; e < 4; e++) { g0[e] = fmaxf(g0[e], 0.f); g1[e] = fmaxf(g1[e], 0.f); }

        // layer 3: 64 -> 128, linear  (lane owns lane, +32, +64, +96)
        float h0[4], h1v[4], h2v[4], h3v[4];
#pragma unroll
        for (int e = 0; e < 4; e++) {
            h0[e]  = sb3[lane];       h1v[e] = sb3[lane + 32];
            h2v[e] = sb3[lane + 64];  h3v[e] = sb3[lane + 96];
        }
#pragma unroll
        for (int i = 0; i < 64; i++) {
            float w0 = sW3[i * 128 + lane];
            float w1 = sW3[i * 128 + 32 + lane];
            float w2 = sW3[i * 128 + 64 + lane];
            float w3 = sW3[i * 128 + 96 + lane];
#pragma unroll
            for (int e = 0; e < 4; e++) {
                float v = (i < 32) ? __shfl_sync(0xffffffffu, g0[e], i)
                                   : __shfl_sync(0xffffffffu, g1[e], i - 32);
                h0[e]  = fmaf(v, w0, h0[e]);
                h1v[e] = fmaf(v, w1, h1v[e]);
                h2v[e] = fmaf(v, w2, h2v[e]);
                h3v[e] = fmaf(v, w3, h3v[e]);
            }
        }
#pragma unroll
        for (int e = 0; e < 4; e++) {
            if (e < nv) {
                m0 = fmaxf(m0, h0[e]);  m1 = fmaxf(m1, h1v[e]);
                m2 = fmaxf(m2, h2v[e]); m3 = fmaxf(m3, h3v[e]);
            }
        }
    };

    // neighbor edges (valid edges are the first cnt, contiguous)
    for (int eb = 0; eb < cnt; eb += 4) {
        int nv = min(4, cnt - eb);
        int rows[4];
#pragma unroll
        for (int e = 0; e < 4; e++) {
            int kk = eb + ((e < nv) ? e : 0);
            rows[e] = b * NN + g_nbr[c * KK + kk];
        }
        process4(rows, nv);
    }
    // self edge: x[dflat], pos[dflat] - center, with dflat = b*S + s (flat!)
    {
        int dflat = b * SS + s;
        int rows[4] = { dflat, dflat, dflat, dflat };
        process4(rows, 1);
    }

    out_x[(size_t)c * HOUT + lane]      = m0;
    out_x[(size_t)c * HOUT + lane + 32] = m1;
    out_x[(size_t)c * HOUT + lane + 64] = m2;
    out_x[(size_t)c * HOUT + lane + 96] = m3;
}

// ===========================================================================
// launch
// ===========================================================================
extern "C" void kernel_launch(void* const* d_in, const int* in_sizes, int n_in,
                              void* d_out, int out_size)
{
    const float* x   = (const float*)d_in[0];
    const float* pos = (const float*)d_in[1];
    // d_in[2] = batch (int32) — unused (implied by layout)
    const float* W1 = (const float*)d_in[3];
    const float* B1 = (const float*)d_in[4];
    const float* W2 = (const float*)d_in[5];
    const float* B2 = (const float*)d_in[6];
    const float* W3 = (const float*)d_in[7];
    const float* B3 = (const float*)d_in[8];

    float* out_x = (float*)d_out;                  // [B*S, 128]
    float* out_c = out_x + (size_t)BB * SS * HOUT; // [B*S, 3]
    float* out_b = out_c + (size_t)BB * SS * 3;    // [B*S]

    const size_t fps_smem = (size_t)3 * NN * sizeof(float);       // 192 KB
    const size_t mlp_smem = (size_t)13760 * sizeof(float);        // ~54 KB
    cudaFuncSetAttribute(fps_kernel, cudaFuncAttributeMaxDynamicSharedMemorySize, (int)fps_smem);
    cudaFuncSetAttribute(mlp_kernel, cudaFuncAttributeMaxDynamicSharedMemorySize, (int)mlp_smem);

    fps_kernel<<<BB, 1024, fps_smem>>>(pos, out_c);
    ballq_kernel<<<(BB * SS * 32) / 256, 256>>>(pos, out_b);
    mlp_kernel<<<(BB * SS) / 8, 256, mlp_smem>>>(x, pos, W1, B1, W2, B2, W3, B3, out_x);
}

// round 3
// speedup vs baseline: 1.0787x; 1.0787x over previous
#include <cuda_runtime.h>
#include <cstdint>

// ---------------------------------------------------------------------------
// SetAbstraction (PointNet++): FPS -> ball query -> MLP -> max
// B=2, N=16384, S=4096, K=32, F_IN=16, hidden 64-64-128
// Round 2: grid-pruned exact FPS (spatial counting sort + per-cell cached
// argmax keys + conservative bbox lower-bound pruning). Bit-identical
// selection sequence to the naive scan.
// ---------------------------------------------------------------------------

#define BB   2
#define NN   16384
#define SS   4096
#define KK   32
#define FIN  16
#define HOUT 128
#define GC    8
#define NCELL 512          // GC^3
#define CW    0.125f       // 1/GC

// ---- scratch (__device__ globals; no allocation allowed) -------------------
__device__ float g_centers[BB * SS * 3];
__device__ int   g_nbr[BB * SS * KK];
__device__ int   g_cnt[BB * SS];

__device__ float g_sx[BB * NN], g_sy[BB * NN], g_sz[BB * NN];
__device__ int   g_sidx[BB * NN];
__device__ int   g_hist[BB * NCELL];
__device__ int   g_cstart[BB * (NCELL + 1)];
__device__ int   g_fill[BB * NCELL];

__device__ __forceinline__ int cell_of(float x, float y, float z) {
    int ix = (int)(x * (float)GC); ix = ix < 0 ? 0 : (ix > GC - 1 ? GC - 1 : ix);
    int iy = (int)(y * (float)GC); iy = iy < 0 ? 0 : (iy > GC - 1 ? GC - 1 : iy);
    int iz = (int)(z * (float)GC); iz = iz < 0 ? 0 : (iz > GC - 1 ? GC - 1 : iz);
    return (iz * GC + iy) * GC + ix;
}

// ===========================================================================
// Preprocessing: histogram -> scan -> scatter (counting sort by cell)
// ===========================================================================
__global__ void init_hist_kernel() {
    int i = blockIdx.x * blockDim.x + threadIdx.x;
    if (i < BB * NCELL) g_hist[i] = 0;
}

__global__ void cell_count_kernel(const float* __restrict__ pos) {
    int i = blockIdx.x * blockDim.x + threadIdx.x;
    if (i >= BB * NN) return;
    int b = i >> 14;
    float x = pos[(size_t)i * 3 + 0], y = pos[(size_t)i * 3 + 1], z = pos[(size_t)i * 3 + 2];
    atomicAdd(&g_hist[b * NCELL + cell_of(x, y, z)], 1);
}

__global__ void cell_scan_kernel() {
    __shared__ int sh[NCELL];
    __shared__ int ss[NCELL + 1];
    int b = blockIdx.x, tid = threadIdx.x;
    if (tid < NCELL) sh[tid] = g_hist[b * NCELL + tid];
    __syncthreads();
    if (tid == 0) {
        int acc = 0;
        for (int c = 0; c < NCELL; c++) { ss[c] = acc; acc += sh[c]; }
        ss[NCELL] = acc;
    }
    __syncthreads();
    if (tid < NCELL) {
        g_cstart[b * (NCELL + 1) + tid] = ss[tid];
        g_fill[b * NCELL + tid] = ss[tid];
    }
    if (tid == 0) g_cstart[b * (NCELL + 1) + NCELL] = ss[NCELL];
}

__global__ void cell_scatter_kernel(const float* __restrict__ pos) {
    int i = blockIdx.x * blockDim.x + threadIdx.x;
    if (i >= BB * NN) return;
    int b = i >> 14;
    int li = i & (NN - 1);
    float x = pos[(size_t)i * 3 + 0], y = pos[(size_t)i * 3 + 1], z = pos[(size_t)i * 3 + 2];
    int c = cell_of(x, y, z);
    int p = atomicAdd(&g_fill[b * NCELL + c], 1);
    g_sx[b * NN + p] = x;
    g_sy[b * NN + p] = y;
    g_sz[b * NN + p] = z;
    g_sidx[b * NN + p] = li;   // original within-batch index (tie-break key)
}

// ===========================================================================
// Kernel 1: grid-pruned exact FPS. One block per batch, 1024 threads.
// smem: sorted (x,y) 128KB + dmin 64KB (dynamic); z & orig-idx from L2.
// Per-cell cached key (max dmin, lowest orig idx, sorted pos); a cell is
// skipped when lb(center, cellbox)*margin >= cached max  (exact: no point
// in the cell can lower its dmin, so key stays valid).
// ===========================================================================
__global__ void __launch_bounds__(1024, 1)
fps_pruned_kernel(const float* __restrict__ pos, float* __restrict__ out_centers)
{
    extern __shared__ float sm[];
    float* s_xy   = sm;            // 2*NN
    float* s_dmin = sm + 2 * NN;   // NN

    __shared__ float s_kv[NCELL];
    __shared__ int   s_ki[NCELL];
    __shared__ int   s_kp[NCELL];
    __shared__ int   s_cs[NCELL + 1];
    __shared__ short s_work[NCELL];
    __shared__ int   s_nwork;
    __shared__ float s_rv[16];
    __shared__ int   s_ri[16];
    __shared__ int   s_rp[16];
    __shared__ float s_c[3];

    const int b = blockIdx.x, tid = threadIdx.x;
    const int base = b * NN;

    for (int p = tid; p < NN; p += 1024) {
        s_xy[2 * p + 0] = g_sx[base + p];
        s_xy[2 * p + 1] = g_sy[base + p];
        s_dmin[p] = 1e10f;
    }
    if (tid < NCELL) { s_kv[tid] = 1e10f; s_ki[tid] = 0; s_kp[tid] = 0; }
    for (int c = tid; c <= NCELL; c += 1024) s_cs[c] = g_cstart[b * (NCELL + 1) + c];
    if (tid == 0) {
        // t = 0: deterministic start at original point 0
        float cx = pos[(size_t)base * 3 + 0];
        float cy = pos[(size_t)base * 3 + 1];
        float cz = pos[(size_t)base * 3 + 2];
        s_c[0] = cx; s_c[1] = cy; s_c[2] = cz;
        int row = b * SS;
        out_centers[row * 3 + 0] = cx; out_centers[row * 3 + 1] = cy; out_centers[row * 3 + 2] = cz;
        g_centers[row * 3 + 0]   = cx; g_centers[row * 3 + 1]   = cy; g_centers[row * 3 + 2]   = cz;
        s_nwork = 0;
    }
    __syncthreads();

    const int wid = tid >> 5, lane = tid & 31;

    for (int t = 1; t < SS; t++) {
        const float cx = s_c[0], cy = s_c[1], cz = s_c[2];

        // ---- phase 1: prune check + worklist compaction (threads 0..511) ----
        if (tid < NCELL) {
            int cell = tid;
            int ix = cell & 7, iy = (cell >> 3) & 7, iz = cell >> 6;
            float lox = (float)ix * CW - 1e-5f, hix = (float)ix * CW + CW + 1e-5f;
            float loy = (float)iy * CW - 1e-5f, hiy = (float)iy * CW + CW + 1e-5f;
            float loz = (float)iz * CW - 1e-5f, hiz = (float)iz * CW + CW + 1e-5f;
            float dx = fmaxf(fmaxf(lox - cx, cx - hix), 0.f);
            float dy = fmaxf(fmaxf(loy - cy, cy - hiy), 0.f);
            float dz = fmaxf(fmaxf(loz - cz, cz - hiz), 0.f);
            float lb = (dx * dx + dy * dy + dz * dz) * 0.999f;  // conservative
            bool touched = lb < s_kv[cell];
            unsigned m = __ballot_sync(0xffffffffu, touched);
            int wbase = 0;
            if (lane == 0) wbase = atomicAdd(&s_nwork, __popc(m));
            wbase = __shfl_sync(0xffffffffu, wbase, 0);
            if (touched)
                s_work[wbase + __popc(m & ((1u << lane) - 1u))] = (short)cell;
        }
        __syncthreads();
        const int nw = s_nwork;

        // ---- phase 2: update touched cells, recompute their keys ----
        for (int wi = wid; wi < nw; wi += 32) {
            int cell = s_work[wi];
            int st = s_cs[cell], en = s_cs[cell + 1];
            float bv = -1.f; int bi = 0x7fffffff; int bp = 0;
            for (int p0 = st; p0 < en; p0 += 32) {
                int p = p0 + lane;
                if (p < en) {
                    float x_ = s_xy[2 * p + 0];
                    float y_ = s_xy[2 * p + 1];
                    float z_ = g_sz[base + p];
                    int   oi = g_sidx[base + p];
                    float dx = __fsub_rn(x_, cx);
                    float dy = __fsub_rn(y_, cy);
                    float dz = __fsub_rn(z_, cz);
                    float d  = __fadd_rn(__fadd_rn(__fmul_rn(dx, dx), __fmul_rn(dy, dy)),
                                         __fmul_rn(dz, dz));
                    float dm = fminf(s_dmin[p], d);
                    s_dmin[p] = dm;
                    if (dm > bv || (dm == bv && oi < bi)) { bv = dm; bi = oi; bp = p; }
                }
            }
#pragma unroll
            for (int off = 16; off > 0; off >>= 1) {
                float ov = __shfl_down_sync(0xffffffffu, bv, off);
                int   o2 = __shfl_down_sync(0xffffffffu, bi, off);
                int   op = __shfl_down_sync(0xffffffffu, bp, off);
                if (ov > bv || (ov == bv && o2 < bi)) { bv = ov; bi = o2; bp = op; }
            }
            if (lane == 0) { s_kv[cell] = bv; s_ki[cell] = bi; s_kp[cell] = bp; }
        }
        __syncthreads();

        // ---- phase 3: argmax over 512 cell keys ----
        if (tid < NCELL) {
            float v = s_kv[tid]; int i_ = s_ki[tid]; int p_ = s_kp[tid];
#pragma unroll
            for (int off = 16; off > 0; off >>= 1) {
                float ov = __shfl_down_sync(0xffffffffu, v, off);
                int   o2 = __shfl_down_sync(0xffffffffu, i_, off);
                int   op = __shfl_down_sync(0xffffffffu, p_, off);
                if (ov > v || (ov == v && o2 < i_)) { v = ov; i_ = o2; p_ = op; }
            }
            if (lane == 0) { s_rv[wid] = v; s_ri[wid] = i_; s_rp[wid] = p_; }
        }
        __syncthreads();
        if (tid < 32) {
            float v = (tid < 16) ? s_rv[tid] : -2.f;
            int  i_ = (tid < 16) ? s_ri[tid] : 0x7fffffff;
            int  p_ = (tid < 16) ? s_rp[tid] : 0;
#pragma unroll
            for (int off = 8; off > 0; off >>= 1) {
                float ov = __shfl_down_sync(0xffffffffu, v, off);
                int   o2 = __shfl_down_sync(0xffffffffu, i_, off);
                int   op = __shfl_down_sync(0xffffffffu, p_, off);
                if (ov > v || (ov == v && o2 < i_)) { v = ov; i_ = o2; p_ = op; }
            }
            if (tid == 0) {
                float ncx = s_xy[2 * p_ + 0];
                float ncy = s_xy[2 * p_ + 1];
                float ncz = g_sz[base + p_];
                s_c[0] = ncx; s_c[1] = ncy; s_c[2] = ncz;
                int row = b * SS + t;
                out_centers[row * 3 + 0] = ncx; out_centers[row * 3 + 1] = ncy; out_centers[row * 3 + 2] = ncz;
                g_centers[row * 3 + 0]   = ncx; g_centers[row * 3 + 1]   = ncy; g_centers[row * 3 + 2]   = ncz;
                s_nwork = 0;
            }
        }
        __syncthreads();
    }
}

// ===========================================================================
// Kernel 2: Ball query — one warp per center; ordered scan, first K within R.
// ===========================================================================
__global__ void __launch_bounds__(256, 8)
ballq_kernel(const float* __restrict__ pos, float* __restrict__ out_batch)
{
    const int w    = (blockIdx.x * blockDim.x + threadIdx.x) >> 5;
    const int lane = threadIdx.x & 31;
    if (w >= BB * SS) return;

    const int b = w >> 12;
    const int s = w & (SS - 1);
    const float* pb = pos + (size_t)b * NN * 3;

    const float cx = g_centers[w * 3 + 0];
    const float cy = g_centers[w * 3 + 1];
    const float cz = g_centers[w * 3 + 2];
    const float R2 = (float)(0.1 * 0.1);
    const int excl = s - b * (NN - SS);

    int cnt = 0;
    for (int j0 = 0; j0 < NN && cnt < KK; j0 += 32) {
        int j = j0 + lane;
        float x_ = pb[j * 3 + 0];
        float y_ = pb[j * 3 + 1];
        float z_ = pb[j * 3 + 2];
        float dx = __fsub_rn(cx, x_);
        float dy = __fsub_rn(cy, y_);
        float dz = __fsub_rn(cz, z_);
        float d2 = __fadd_rn(__fadd_rn(__fmul_rn(dx, dx), __fmul_rn(dy, dy)),
                             __fmul_rn(dz, dz));
        bool hit = (d2 <= R2) && (j != excl);
        unsigned m = __ballot_sync(0xffffffffu, hit);
        while (m && cnt < KK) {
            int bit = __ffs(m) - 1;
            if (lane == bit) g_nbr[w * KK + cnt] = j0 + bit;
            cnt++;
            m &= m - 1;
        }
    }
    if (lane == 0) {
        g_cnt[w] = cnt;
        out_batch[w] = (float)b;
    }
}

// ===========================================================================
// Kernel 3: gather + MLP(19->64->64->128) + max over K+1 (unchanged).
// ===========================================================================
__global__ void __launch_bounds__(256, 1)
mlp_kernel(const float* __restrict__ x, const float* __restrict__ pos,
           const float* __restrict__ W1, const float* __restrict__ B1,
           const float* __restrict__ W2, const float* __restrict__ B2,
           const float* __restrict__ W3, const float* __restrict__ B3,
           float* __restrict__ out_x)
{
    extern __shared__ float sw[];
    float* sW1 = sw;
    float* sb1 = sW1 + 19 * 64;
    float* sW2 = sb1 + 64;
    float* sb2 = sW2 + 4096;
    float* sW3 = sb2 + 64;
    float* sb3 = sW3 + 8192;

    const int tid = threadIdx.x;
    for (int i = tid; i < 19 * 64; i += 256) sW1[i] = W1[i];
    for (int i = tid; i < 64;      i += 256) sb1[i] = B1[i];
    for (int i = tid; i < 64 * 64; i += 256) sW2[i] = W2[i];
    for (int i = tid; i < 64;      i += 256) sb2[i] = B2[i];
    for (int i = tid; i < 64 * 128; i += 256) sW3[i] = W3[i];
    for (int i = tid; i < 128;     i += 256) sb3[i] = B3[i];
    __syncthreads();

    const int lane = tid & 31;
    const int c    = blockIdx.x * 8 + (tid >> 5);
    const int b    = c >> 12;
    const int s    = c & (SS - 1);

    const float cx = g_centers[c * 3 + 0];
    const float cy = g_centers[c * 3 + 1];
    const float cz = g_centers[c * 3 + 2];
    const float ccomp = (lane == 16) ? cx : ((lane == 17) ? cy : cz);
    const int cnt = g_cnt[c];

    float m0 = -3.0e38f, m1 = -3.0e38f, m2 = -3.0e38f, m3 = -3.0e38f;

    auto process4 = [&](const int rows[4], int nv) {
        float fv[4];
#pragma unroll
        for (int e = 0; e < 4; e++) {
            int r = rows[e];
            float v = 0.f;
            if (lane < FIN)          v = x[(size_t)r * FIN + lane];
            else if (lane < FIN + 3) v = pos[(size_t)r * 3 + (lane - FIN)] - ccomp;
            fv[e] = (e < nv) ? v : 0.f;
        }
        float a0[4], a1[4];
#pragma unroll
        for (int e = 0; e < 4; e++) { a0[e] = sb1[lane]; a1[e] = sb1[lane + 32]; }
#pragma unroll
        for (int i = 0; i < FIN + 3; i++) {
            float w0 = sW1[i * 64 + lane];
            float w1 = sW1[i * 64 + 32 + lane];
#pragma unroll
            for (int e = 0; e < 4; e++) {
                float v = __shfl_sync(0xffffffffu, fv[e], i);
                a0[e] = fmaf(v, w0, a0[e]);
                a1[e] = fmaf(v, w1, a1[e]);
            }
        }
#pragma unroll
        for (int e = 0; e < 4; e++) { a0[e] = fmaxf(a0[e], 0.f); a1[e] = fmaxf(a1[e], 0.f); }

        float g0[4], g1[4];
#pragma unroll
        for (int e = 0; e < 4; e++) { g0[e] = sb2[lane]; g1[e] = sb2[lane + 32]; }
#pragma unroll
        for (int i = 0; i < 64; i++) {
            float w0 = sW2[i * 64 + lane];
            float w1 = sW2[i * 64 + 32 + lane];
#pragma unroll
            for (int e = 0; e < 4; e++) {
                float v = (i < 32) ? __shfl_sync(0xffffffffu, a0[e], i)
                                   : __shfl_sync(0xffffffffu, a1[e], i - 32);
                g0[e] = fmaf(v, w0, g0[e]);
                g1[e] = fmaf(v, w1, g1[e]);
            }
        }
#pragma unroll
        for (int e = 0; e < 4; e++) { g0[e] = fmaxf(g0[e], 0.f); g1[e] = fmaxf(g1[e], 0.f); }

        float h0[4], h1v[4], h2v[4], h3v[4];
#pragma unroll
        for (int e = 0; e < 4; e++) {
            h0[e]  = sb3[lane];       h1v[e] = sb3[lane + 32];
            h2v[e] = sb3[lane + 64];  h3v[e] = sb3[lane + 96];
        }
#pragma unroll
        for (int i = 0; i < 64; i++) {
            float w0 = sW3[i * 128 + lane];
            float w1 = sW3[i * 128 + 32 + lane];
            float w2 = sW3[i * 128 + 64 + lane];
            float w3 = sW3[i * 128 + 96 + lane];
#pragma unroll
            for (int e = 0; e < 4; e++) {
                float v = (i < 32) ? __shfl_sync(0xffffffffu, g0[e], i)
                                   : __shfl_sync(0xffffffffu, g1[e], i - 32);
                h0[e]  = fmaf(v, w0, h0[e]);
                h1v[e] = fmaf(v, w1, h1v[e]);
                h2v[e] = fmaf(v, w2, h2v[e]);
                h3v[e] = fmaf(v, w3, h3v[e]);
            }
        }
#pragma unroll
        for (int e = 0; e < 4; e++) {
            if (e < nv) {
                m0 = fmaxf(m0, h0[e]);  m1 = fmaxf(m1, h1v[e]);
                m2 = fmaxf(m2, h2v[e]); m3 = fmaxf(m3, h3v[e]);
            }
        }
    };

    for (int eb = 0; eb < cnt; eb += 4) {
        int nv = min(4, cnt - eb);
        int rows[4];
#pragma unroll
        for (int e = 0; e < 4; e++) {
            int kk = eb + ((e < nv) ? e : 0);
            rows[e] = b * NN + g_nbr[c * KK + kk];
        }
        process4(rows, nv);
    }
    {
        int dflat = b * SS + s;
        int rows[4] = { dflat, dflat, dflat, dflat };
        process4(rows, 1);
    }

    out_x[(size_t)c * HOUT + lane]      = m0;
    out_x[(size_t)c * HOUT + lane + 32] = m1;
    out_x[(size_t)c * HOUT + lane + 64] = m2;
    out_x[(size_t)c * HOUT + lane + 96] = m3;
}

// ===========================================================================
// launch
// ===========================================================================
extern "C" void kernel_launch(void* const* d_in, const int* in_sizes, int n_in,
                              void* d_out, int out_size)
{
    const float* x   = (const float*)d_in[0];
    const float* pos = (const float*)d_in[1];
    const float* W1 = (const float*)d_in[3];
    const float* B1 = (const float*)d_in[4];
    const float* W2 = (const float*)d_in[5];
    const float* B2 = (const float*)d_in[6];
    const float* W3 = (const float*)d_in[7];
    const float* B3 = (const float*)d_in[8];

    float* out_x = (float*)d_out;
    float* out_c = out_x + (size_t)BB * SS * HOUT;
    float* out_b = out_c + (size_t)BB * SS * 3;

    const size_t fps_smem = (size_t)3 * NN * sizeof(float);   // 192 KB
    const size_t mlp_smem = (size_t)13760 * sizeof(float);
    cudaFuncSetAttribute(fps_pruned_kernel, cudaFuncAttributeMaxDynamicSharedMemorySize, (int)fps_smem);
    cudaFuncSetAttribute(mlp_kernel, cudaFuncAttributeMaxDynamicSharedMemorySize, (int)mlp_smem);

    init_hist_kernel<<<(BB * NCELL + 255) / 256, 256>>>();
    cell_count_kernel<<<(BB * NN + 255) / 256, 256>>>(pos);
    cell_scan_kernel<<<BB, NCELL>>>();
    cell_scatter_kernel<<<(BB * NN + 255) / 256, 256>>>(pos);
    fps_pruned_kernel<<<BB, 1024, fps_smem>>>(pos, out_c);
    ballq_kernel<<<(BB * SS * 32) / 256, 256>>>(pos, out_b);
    mlp_kernel<<<(BB * SS) / 8, 256, mlp_smem>>>(x, pos, W1, B1, W2, B2, W3, B3, out_x);
}

// round 4
// speedup vs baseline: 1.3225x; 1.2260x over previous
#include <cuda_runtime.h>
#include <cstdint>

// ---------------------------------------------------------------------------
// SetAbstraction (PointNet++): FPS -> ball query -> MLP -> max
// B=2, N=16384, S=4096, K=32, F_IN=16, hidden 64-64-128
// Round 4 FPS: static cell ownership (keys in registers), fused int2 z/idx
// loads, REDUX argmax, 2 barriers/iter, pipelined cell prefetch.
// Selection sequence bit-identical to the naive scan.
// ---------------------------------------------------------------------------

#define BB   2
#define NN   16384
#define SS   4096
#define KK   32
#define FIN  16
#define HOUT 128
#define GC    8
#define NCELL 512
#define CW    0.125f
#define FULLM 0xffffffffu

// ---- scratch (__device__ globals; no allocation allowed) -------------------
__device__ float g_centers[BB * SS * 3];
__device__ int   g_nbr[BB * SS * KK];
__device__ int   g_cnt[BB * SS];

__device__ float2 g_sxy[BB * NN];      // sorted (x,y)
__device__ int2   g_szi[BB * NN];      // sorted (z bits, orig idx)
__device__ int    g_hist[BB * NCELL];
__device__ int    g_cstart[BB * (NCELL + 1)];
__device__ int    g_fill[BB * NCELL];

__device__ __forceinline__ int cell_of(float x, float y, float z) {
    int ix = (int)(x * (float)GC); ix = ix < 0 ? 0 : (ix > GC - 1 ? GC - 1 : ix);
    int iy = (int)(y * (float)GC); iy = iy < 0 ? 0 : (iy > GC - 1 ? GC - 1 : iy);
    int iz = (int)(z * (float)GC); iz = iz < 0 ? 0 : (iz > GC - 1 ? GC - 1 : iz);
    return (iz * GC + iy) * GC + ix;
}

// ===========================================================================
// Preprocessing: histogram -> scan -> scatter (counting sort by cell)
// ===========================================================================
__global__ void init_hist_kernel() {
    int i = blockIdx.x * blockDim.x + threadIdx.x;
    if (i < BB * NCELL) g_hist[i] = 0;
}

__global__ void cell_count_kernel(const float* __restrict__ pos) {
    int i = blockIdx.x * blockDim.x + threadIdx.x;
    if (i >= BB * NN) return;
    int b = i >> 14;
    float x = pos[(size_t)i * 3 + 0], y = pos[(size_t)i * 3 + 1], z = pos[(size_t)i * 3 + 2];
    atomicAdd(&g_hist[b * NCELL + cell_of(x, y, z)], 1);
}

__global__ void cell_scan_kernel() {
    __shared__ int sh[NCELL];
    __shared__ int ss[NCELL + 1];
    int b = blockIdx.x, tid = threadIdx.x;
    if (tid < NCELL) sh[tid] = g_hist[b * NCELL + tid];
    __syncthreads();
    if (tid == 0) {
        int acc = 0;
        for (int c = 0; c < NCELL; c++) { ss[c] = acc; acc += sh[c]; }
        ss[NCELL] = acc;
    }
    __syncthreads();
    if (tid < NCELL) {
        g_cstart[b * (NCELL + 1) + tid] = ss[tid];
        g_fill[b * NCELL + tid] = ss[tid];
    }
    if (tid == 0) g_cstart[b * (NCELL + 1) + NCELL] = ss[NCELL];
}

__global__ void cell_scatter_kernel(const float* __restrict__ pos) {
    int i = blockIdx.x * blockDim.x + threadIdx.x;
    if (i >= BB * NN) return;
    int b = i >> 14;
    int li = i & (NN - 1);
    float x = pos[(size_t)i * 3 + 0], y = pos[(size_t)i * 3 + 1], z = pos[(size_t)i * 3 + 2];
    int c = cell_of(x, y, z);
    int p = atomicAdd(&g_fill[b * NCELL + c], 1);
    g_sxy[b * NN + p] = make_float2(x, y);
    g_szi[b * NN + p] = make_int2(__float_as_int(z), li);
}

// warp argmax over (u32 key, min-origidx tiebreak) via REDUX; returns src lane
__device__ __forceinline__ int warp_argmax(unsigned bu, int boi, unsigned& out_max) {
    unsigned wm = __reduce_max_sync(FULLM, bu);
    out_max = wm;
    unsigned eq = __ballot_sync(FULLM, bu == wm);
    if (__popc(eq) == 1) return __ffs(eq) - 1;
    unsigned cand = (bu == wm) ? (unsigned)boi : 0xffffffffu;
    unsigned mo = __reduce_min_sync(FULLM, cand);
    return __ffs(__ballot_sync(FULLM, cand == mo)) - 1;
}

// ===========================================================================
// Kernel 1: grid-pruned exact FPS. One block per batch, 512 threads (16 warps).
// Warp w owns cells {w + 16*l}; lane l keeps its cell's key in registers.
// smem: sorted (x,y) 128KB + dmin 64KB. z+origidx fused int2 from L2.
// ===========================================================================
__global__ void __launch_bounds__(512, 1)
fps_kernel(const float* __restrict__ pos, float* __restrict__ out_centers)
{
    extern __shared__ float sm[];
    float2* s_xy   = (float2*)sm;        // NN float2
    float*  s_dmin = sm + 2 * NN;        // NN floats

    __shared__ unsigned s_rv[16];
    __shared__ int      s_ri[16];
    __shared__ int      s_rp[16];
    __shared__ float    s_rz[16];
    __shared__ float    s_c[3];

    const int b = blockIdx.x, tid = threadIdx.x;
    const int w = tid >> 5, lane = tid & 31;
    const int base = b * NN;

    for (int p = tid; p < NN; p += 512) {
        s_xy[p] = g_sxy[base + p];
        s_dmin[p] = 1e10f;
    }

    // this lane's owned cell
    const int cell = w + (lane << 4);
    const int cs0 = g_cstart[b * (NCELL + 1) + cell];
    const int cs1 = g_cstart[b * (NCELL + 1) + cell + 1];
    const int ix = cell & 7, iy = (cell >> 3) & 7, iz = cell >> 6;
    const float lox = (float)ix * CW - 1e-5f, hix = (float)ix * CW + CW + 1e-5f;
    const float loy = (float)iy * CW - 1e-5f, hiy = (float)iy * CW + CW + 1e-5f;
    const float loz = (float)iz * CW - 1e-5f, hiz = (float)iz * CW + CW + 1e-5f;

    unsigned kv = __float_as_uint(1e10f);   // cell key: max dmin (as u32 bits, >=0)
    int      ki = 0x7fffffff;               // winner orig idx
    int      kp = 0;                        // winner sorted pos
    float    kz = 0.f;                      // winner z

    if (tid == 0) {
        float cx = pos[(size_t)base * 3 + 0];
        float cy = pos[(size_t)base * 3 + 1];
        float cz = pos[(size_t)base * 3 + 2];
        s_c[0] = cx; s_c[1] = cy; s_c[2] = cz;
        int row = b * SS;
        out_centers[row * 3 + 0] = cx; out_centers[row * 3 + 1] = cy; out_centers[row * 3 + 2] = cz;
        g_centers[row * 3 + 0]   = cx; g_centers[row * 3 + 1]   = cy; g_centers[row * 3 + 2]   = cz;
    }
    __syncthreads();

    for (int t = 1; t < SS; t++) {
        const float cx = s_c[0], cy = s_c[1], cz = s_c[2];

        // --- prune: each lane checks its own cell -------------------------
        float pdx = fmaxf(fmaxf(lox - cx, cx - hix), 0.f);
        float pdy = fmaxf(fmaxf(loy - cy, cy - hiy), 0.f);
        float pdz = fmaxf(fmaxf(loz - cz, cz - hiz), 0.f);
        float lb  = (pdx * pdx + pdy * pdy + pdz * pdz) * 0.999f;
        bool touched = lb < __uint_as_float(kv);
        unsigned tmask = __ballot_sync(FULLM, touched);
        const bool any = (tmask != 0);

        // --- process touched cells (pipelined: prefetch next cell) --------
        int j = -1, st = 0, en = 0; bool v = false;
        int2 zi = make_int2(0, 0x7fffffff); float2 xy = make_float2(0.f, 0.f);
        if (tmask) {
            j = __ffs(tmask) - 1; tmask &= tmask - 1;
            st = __shfl_sync(FULLM, cs0, j);
            en = __shfl_sync(FULLM, cs1, j);
            int p = st + lane; v = p < en;
            if (v) { zi = g_szi[base + p]; xy = s_xy[p]; }
        }
        while (j >= 0) {
            unsigned bu = 0u; int boi = 0x7fffffff; int bp = 0; float bz = 0.f;
            // chunk 0 (preloaded)
            if (v) {
                int p = st + lane;
                float zz  = __int_as_float(zi.x);
                float ddx = __fsub_rn(xy.x, cx);
                float ddy = __fsub_rn(xy.y, cy);
                float ddz = __fsub_rn(zz,   cz);
                float d   = __fadd_rn(__fadd_rn(__fmul_rn(ddx, ddx), __fmul_rn(ddy, ddy)),
                                      __fmul_rn(ddz, ddz));
                float dm  = fminf(s_dmin[p], d);
                s_dmin[p] = dm;
                unsigned du = __float_as_uint(dm);
                if (du > bu || (du == bu && zi.y < boi)) { bu = du; boi = zi.y; bp = p; bz = zz; }
            }
            // prefetch next touched cell's first chunk
            int jn = -1, stn = 0, enn = 0; bool vn = false;
            int2 zin = make_int2(0, 0x7fffffff); float2 xyn = make_float2(0.f, 0.f);
            if (tmask) {
                jn = __ffs(tmask) - 1; tmask &= tmask - 1;
                stn = __shfl_sync(FULLM, cs0, jn);
                enn = __shfl_sync(FULLM, cs1, jn);
                int p = stn + lane; vn = p < enn;
                if (vn) { zin = g_szi[base + p]; xyn = s_xy[p]; }
            }
            // remaining chunks of current cell (cells > 32 points)
            for (int p0 = st + 32; p0 < en; p0 += 32) {
                int p = p0 + lane;
                if (p < en) {
                    int2   z2 = g_szi[base + p];
                    float2 x2 = s_xy[p];
                    float zz  = __int_as_float(z2.x);
                    float ddx = __fsub_rn(x2.x, cx);
                    float ddy = __fsub_rn(x2.y, cy);
                    float ddz = __fsub_rn(zz,   cz);
                    float d   = __fadd_rn(__fadd_rn(__fmul_rn(ddx, ddx), __fmul_rn(ddy, ddy)),
                                          __fmul_rn(ddz, ddz));
                    float dm  = fminf(s_dmin[p], d);
                    s_dmin[p] = dm;
                    unsigned du = __float_as_uint(dm);
                    if (du > bu || (du == bu && z2.y < boi)) { bu = du; boi = z2.y; bp = p; bz = zz; }
                }
            }
            // recompute this cell's key (REDUX argmax, tie -> min orig idx)
            unsigned wm;
            int srcl = warp_argmax(bu, boi, wm);
            int   nki = __shfl_sync(FULLM, boi, srcl);
            int   nkp = __shfl_sync(FULLM, bp,  srcl);
            float nkz = __shfl_sync(FULLM, bz,  srcl);
            if (lane == j) { kv = wm; ki = nki; kp = nkp; kz = nkz; }
            j = jn; st = stn; en = enn; v = vn; zi = zin; xy = xyn;
        }

        // --- per-warp partial over its 32 owned cells (skip if unchanged) --
        if (any) {
            unsigned wm;
            int srcl = warp_argmax(kv, ki, wm);
            if (lane == srcl) { s_rv[w] = wm; s_ri[w] = ki; s_rp[w] = kp; s_rz[w] = kz; }
        }
        __syncthreads();

        // --- warp 0: final argmax over 16 partials, publish center --------
        if (w == 0) {
            unsigned mv = (lane < 16) ? s_rv[lane] : 0u;
            int      mi = (lane < 16) ? s_ri[lane] : 0x7fffffff;
            int      mp = (lane < 16) ? s_rp[lane] : 0;
            float    mz = (lane < 16) ? s_rz[lane] : 0.f;
            unsigned wm;
            int srcl = warp_argmax(mv, mi, wm);
            if (lane == srcl) {
                float2 xyw = s_xy[mp];
                s_c[0] = xyw.x; s_c[1] = xyw.y; s_c[2] = mz;
                int row = b * SS + t;
                out_centers[row * 3 + 0] = xyw.x; out_centers[row * 3 + 1] = xyw.y; out_centers[row * 3 + 2] = mz;
                g_centers[row * 3 + 0]   = xyw.x; g_centers[row * 3 + 1]   = xyw.y; g_centers[row * 3 + 2]   = mz;
            }
        }
        __syncthreads();
    }
}

// ===========================================================================
// Kernel 2: Ball query — one warp per center; ordered scan, first K within R.
// ===========================================================================
__global__ void __launch_bounds__(256, 8)
ballq_kernel(const float* __restrict__ pos, float* __restrict__ out_batch)
{
    const int w    = (blockIdx.x * blockDim.x + threadIdx.x) >> 5;
    const int lane = threadIdx.x & 31;
    if (w >= BB * SS) return;

    const int b = w >> 12;
    const int s = w & (SS - 1);
    const float* pb = pos + (size_t)b * NN * 3;

    const float cx = g_centers[w * 3 + 0];
    const float cy = g_centers[w * 3 + 1];
    const float cz = g_centers[w * 3 + 2];
    const float R2 = (float)(0.1 * 0.1);
    const int excl = s - b * (NN - SS);

    int cnt = 0;
    for (int j0 = 0; j0 < NN && cnt < KK; j0 += 32) {
        int j = j0 + lane;
        float x_ = pb[j * 3 + 0];
        float y_ = pb[j * 3 + 1];
        float z_ = pb[j * 3 + 2];
        float dx = __fsub_rn(cx, x_);
        float dy = __fsub_rn(cy, y_);
        float dz = __fsub_rn(cz, z_);
        float d2 = __fadd_rn(__fadd_rn(__fmul_rn(dx, dx), __fmul_rn(dy, dy)),
                             __fmul_rn(dz, dz));
        bool hit = (d2 <= R2) && (j != excl);
        unsigned m = __ballot_sync(0xffffffffu, hit);
        while (m && cnt < KK) {
            int bit = __ffs(m) - 1;
            if (lane == bit) g_nbr[w * KK + cnt] = j0 + bit;
            cnt++;
            m &= m - 1;
        }
    }
    if (lane == 0) {
        g_cnt[w] = cnt;
        out_batch[w] = (float)b;
    }
}

// ===========================================================================
// Kernel 3: gather + MLP(19->64->64->128) + max over K+1 (unchanged).
// ===========================================================================
__global__ void __launch_bounds__(256, 1)
mlp_kernel(const float* __restrict__ x, const float* __restrict__ pos,
           const float* __restrict__ W1, const float* __restrict__ B1,
           const float* __restrict__ W2, const float* __restrict__ B2,
           const float* __restrict__ W3, const float* __restrict__ B3,
           float* __restrict__ out_x)
{
    extern __shared__ float sw[];
    float* sW1 = sw;
    float* sb1 = sW1 + 19 * 64;
    float* sW2 = sb1 + 64;
    float* sb2 = sW2 + 4096;
    float* sW3 = sb2 + 64;
    float* sb3 = sW3 + 8192;

    const int tid = threadIdx.x;
    for (int i = tid; i < 19 * 64; i += 256) sW1[i] = W1[i];
    for (int i = tid; i < 64;      i += 256) sb1[i] = B1[i];
    for (int i = tid; i < 64 * 64; i += 256) sW2[i] = W2[i];
    for (int i = tid; i < 64;      i += 256) sb2[i] = B2[i];
    for (int i = tid; i < 64 * 128; i += 256) sW3[i] = W3[i];
    for (int i = tid; i < 128;     i += 256) sb3[i] = B3[i];
    __syncthreads();

    const int lane = tid & 31;
    const int c    = blockIdx.x * 8 + (tid >> 5);
    const int b    = c >> 12;
    const int s    = c & (SS - 1);

    const float cx = g_centers[c * 3 + 0];
    const float cy = g_centers[c * 3 + 1];
    const float cz = g_centers[c * 3 + 2];
    const float ccomp = (lane == 16) ? cx : ((lane == 17) ? cy : cz);
    const int cnt = g_cnt[c];

    float m0 = -3.0e38f, m1 = -3.0e38f, m2 = -3.0e38f, m3 = -3.0e38f;

    auto process4 = [&](const int rows[4], int nv) {
        float fv[4];
#pragma unroll
        for (int e = 0; e < 4; e++) {
            int r = rows[e];
            float v = 0.f;
            if (lane < FIN)          v = x[(size_t)r * FIN + lane];
            else if (lane < FIN + 3) v = pos[(size_t)r * 3 + (lane - FIN)] - ccomp;
            fv[e] = (e < nv) ? v : 0.f;
        }
        float a0[4], a1[4];
#pragma unroll
        for (int e = 0; e < 4; e++) { a0[e] = sb1[lane]; a1[e] = sb1[lane + 32]; }
#pragma unroll
        for (int i = 0; i < FIN + 3; i++) {
            float w0 = sW1[i * 64 + lane];
            float w1 = sW1[i * 64 + 32 + lane];
#pragma unroll
            for (int e = 0; e < 4; e++) {
                float v = __shfl_sync(0xffffffffu, fv[e], i);
                a0[e] = fmaf(v, w0, a0[e]);
                a1[e] = fmaf(v, w1, a1[e]);
            }
        }
#pragma unroll
        for (int e = 0; e < 4; e++) { a0[e] = fmaxf(a0[e], 0.f); a1[e] = fmaxf(a1[e], 0.f); }

        float g0[4], g1[4];
#pragma unroll
        for (int e = 0; e < 4; e++) { g0[e] = sb2[lane]; g1[e] = sb2[lane + 32]; }
#pragma unroll
        for (int i = 0; i < 64; i++) {
            float w0 = sW2[i * 64 + lane];
            float w1 = sW2[i * 64 + 32 + lane];
#pragma unroll
            for (int e = 0; e < 4; e++) {
                float v = (i < 32) ? __shfl_sync(0xffffffffu, a0[e], i)
                                   : __shfl_sync(0xffffffffu, a1[e], i - 32);
                g0[e] = fmaf(v, w0, g0[e]);
                g1[e] = fmaf(v, w1, g1[e]);
            }
        }
#pragma unroll
        for (int e = 0; e < 4; e++) { g0[e] = fmaxf(g0[e], 0.f); g1[e] = fmaxf(g1[e], 0.f); }

        float h0[4], h1v[4], h2v[4], h3v[4];
#pragma unroll
        for (int e = 0; e < 4; e++) {
            h0[e]  = sb3[lane];       h1v[e] = sb3[lane + 32];
            h2v[e] = sb3[lane + 64];  h3v[e] = sb3[lane + 96];
        }
#pragma unroll
        for (int i = 0; i < 64; i++) {
            float w0 = sW3[i * 128 + lane];
            float w1 = sW3[i * 128 + 32 + lane];
            float w2 = sW3[i * 128 + 64 + lane];
            float w3 = sW3[i * 128 + 96 + lane];
#pragma unroll
            for (int e = 0; e < 4; e++) {
                float v = (i < 32) ? __shfl_sync(0xffffffffu, g0[e], i)
                                   : __shfl_sync(0xffffffffu, g1[e], i - 32);
                h0[e]  = fmaf(v, w0, h0[e]);
                h1v[e] = fmaf(v, w1, h1v[e]);
                h2v[e] = fmaf(v, w2, h2v[e]);
                h3v[e] = fmaf(v, w3, h3v[e]);
            }
        }
#pragma unroll
        for (int e = 0; e < 4; e++) {
            if (e < nv) {
                m0 = fmaxf(m0, h0[e]);  m1 = fmaxf(m1, h1v[e]);
                m2 = fmaxf(m2, h2v[e]); m3 = fmaxf(m3, h3v[e]);
            }
        }
    };

    for (int eb = 0; eb < cnt; eb += 4) {
        int nv = min(4, cnt - eb);
        int rows[4];
#pragma unroll
        for (int e = 0; e < 4; e++) {
            int kk = eb + ((e < nv) ? e : 0);
            rows[e] = b * NN + g_nbr[c * KK + kk];
        }
        process4(rows, nv);
    }
    {
        int dflat = b * SS + s;
        int rows[4] = { dflat, dflat, dflat, dflat };
        process4(rows, 1);
    }

    out_x[(size_t)c * HOUT + lane]      = m0;
    out_x[(size_t)c * HOUT + lane + 32] = m1;
    out_x[(size_t)c * HOUT + lane + 64] = m2;
    out_x[(size_t)c * HOUT + lane + 96] = m3;
}

// ===========================================================================
// launch
// ===========================================================================
extern "C" void kernel_launch(void* const* d_in, const int* in_sizes, int n_in,
                              void* d_out, int out_size)
{
    const float* x   = (const float*)d_in[0];
    const float* pos = (const float*)d_in[1];
    const float* W1 = (const float*)d_in[3];
    const float* B1 = (const float*)d_in[4];
    const float* W2 = (const float*)d_in[5];
    const float* B2 = (const float*)d_in[6];
    const float* W3 = (const float*)d_in[7];
    const float* B3 = (const float*)d_in[8];

    float* out_x = (float*)d_out;
    float* out_c = out_x + (size_t)BB * SS * HOUT;
    float* out_b = out_c + (size_t)BB * SS * 3;

    const size_t fps_smem = (size_t)3 * NN * sizeof(float);   // 192 KB
    const size_t mlp_smem = (size_t)13760 * sizeof(float);
    cudaFuncSetAttribute(fps_kernel, cudaFuncAttributeMaxDynamicSharedMemorySize, (int)fps_smem);
    cudaFuncSetAttribute(mlp_kernel, cudaFuncAttributeMaxDynamicSharedMemorySize, (int)mlp_smem);

    init_hist_kernel<<<(BB * NCELL + 255) / 256, 256>>>();
    cell_count_kernel<<<(BB * NN + 255) / 256, 256>>>(pos);
    cell_scan_kernel<<<BB, NCELL>>>();
    cell_scatter_kernel<<<(BB * NN + 255) / 256, 256>>>(pos);
    fps_kernel<<<BB, 512, fps_smem>>>(pos, out_c);
    ballq_kernel<<<(BB * SS * 32) / 256, 256>>>(pos, out_b);
    mlp_kernel<<<(BB * SS) / 8, 256, mlp_smem>>>(x, pos, W1, B1, W2, B2, W3, B3, out_x);
}